// round 7
// baseline (speedup 1.0000x reference)
#include <cuda_runtime.h>

// N=50000 nodes, E=800000 edges, 8 heads x 32 head_dim keys,
// value rows of 256 floats (64 ch x 4 rep).
#define MAX_N 50000
#define MAX_E 800000
#define NBLK_MAX 256   // ceil(MAX_N/256) = 196 <= 256

// Scratch (allocation-free rule: __device__ globals)
__device__ int g_count[MAX_N];
__device__ int g_off[MAX_N + 1];
__device__ int g_pos[MAX_N];
__device__ int g_eid[MAX_E];
__device__ int g_blocksum[NBLK_MAX];
__device__ int g_blockoff[NBLK_MAX];

__global__ void zero_counts(int n_nodes) {
    int i = blockIdx.x * blockDim.x + threadIdx.x;
    if (i < n_nodes) g_count[i] = 0;
}

__global__ void histogram_kernel(const int* __restrict__ dst, int n_edges) {
    int i = blockIdx.x * blockDim.x + threadIdx.x;
    if (i < n_edges) atomicAdd(&g_count[dst[i]], 1);
}

// ---- two-level scan ------------------------------------------------------
__global__ void block_reduce(int n_nodes) {
    __shared__ int ws[8];
    int tid = threadIdx.x, lane = tid & 31, wid = tid >> 5;
    int i = blockIdx.x * 256 + tid;
    int v = (i < n_nodes) ? g_count[i] : 0;
    #pragma unroll
    for (int d = 16; d >= 1; d >>= 1)
        v += __shfl_xor_sync(0xffffffffu, v, d);
    if (lane == 0) ws[wid] = v;
    __syncthreads();
    if (tid == 0) {
        int s = 0;
        #pragma unroll
        for (int j = 0; j < 8; j++) s += ws[j];
        g_blocksum[blockIdx.x] = s;
    }
}

__global__ void scan_blocks(int nb) {   // 1 block, 256 threads
    __shared__ int warp_incl[8];
    int tid = threadIdx.x, lane = tid & 31, wid = tid >> 5;
    int v = (tid < nb) ? g_blocksum[tid] : 0;
    int x = v;
    #pragma unroll
    for (int d = 1; d < 32; d <<= 1) {
        int y = __shfl_up_sync(0xffffffffu, x, d);
        if (lane >= d) x += y;
    }
    if (lane == 31) warp_incl[wid] = x;
    __syncthreads();
    if (wid == 0 && lane < 8) {
        int s = warp_incl[lane];
        #pragma unroll
        for (int d = 1; d < 8; d <<= 1) {
            int y = __shfl_up_sync(0xffu, s, d);
            if (lane >= d) s += y;
        }
        warp_incl[lane] = s;
    }
    __syncthreads();
    int base = (wid > 0) ? warp_incl[wid - 1] : 0;
    if (tid < nb) g_blockoff[tid] = base + x - v;
}

__global__ void scan_local(int n_nodes) {
    __shared__ int warp_incl[8];
    int tid = threadIdx.x, lane = tid & 31, wid = tid >> 5;
    int i = blockIdx.x * 256 + tid;
    int v = (i < n_nodes) ? g_count[i] : 0;
    int x = v;
    #pragma unroll
    for (int d = 1; d < 32; d <<= 1) {
        int y = __shfl_up_sync(0xffffffffu, x, d);
        if (lane >= d) x += y;
    }
    if (lane == 31) warp_incl[wid] = x;
    __syncthreads();
    if (wid == 0 && lane < 8) {
        int s = warp_incl[lane];
        #pragma unroll
        for (int d = 1; d < 8; d <<= 1) {
            int y = __shfl_up_sync(0xffu, s, d);
            if (lane >= d) s += y;
        }
        warp_incl[lane] = s;
    }
    __syncthreads();
    int wbase = (wid > 0) ? warp_incl[wid - 1] : 0;
    int excl = g_blockoff[blockIdx.x] + wbase + (x - v);
    if (i < n_nodes) {
        g_off[i] = excl;
        g_pos[i] = excl;
        if (i == n_nodes - 1) g_off[n_nodes] = excl + v;
    }
}
// --------------------------------------------------------------------------

__global__ void scatter_edges(const int* __restrict__ dst, int n_edges) {
    int i = blockIdx.x * blockDim.x + threadIdx.x;
    if (i < n_edges) {
        int p = atomicAdd(&g_pos[dst[i]], 1);
        g_eid[p] = i;
    }
}

// Fused attention: one block (256 threads) per node, one warp per head.
// Chunk of 32 edges; each thread keeps the 32 value elements it owns in
// registers (loaded concurrently with the key loads), applies softmax
// weights after the reductions. Warps fully independent.
__global__ void __launch_bounds__(256, 3) attn_kernel(
    const float* __restrict__ key_edge,   // [E, 8, 32]
    const float* __restrict__ q0,         // [N, 64, 1]
    const float* __restrict__ q1,         // [N, 64, 3]
    const float* __restrict__ value,      // [E, 64, 4] == [E, 256]
    float* __restrict__ out)              // [N, 64, 4] == [N, 256]
{
    __shared__ float q_sm[8][32];

    const int n    = blockIdx.x;
    const int tid  = threadIdx.x;
    const int w    = tid >> 5;            // head == warp id
    const int lane = tid & 31;
    const float NEG_INF = __int_as_float(0xff800000);

    // q[n, w, lane]: flat (64,4) index = w*32 + lane -> (channel, rep)
    {
        int c = (w << 3) + (lane >> 2);
        int r = lane & 3;
        q_sm[w][lane] = (r == 0) ? __ldg(&q0[n * 64 + c])
                                 : __ldg(&q1[(n * 64 + c) * 3 + (r - 1)]);
    }
    __syncwarp();

    const int beg = g_off[n];
    const int deg = g_off[n + 1] - beg;
    const float* vbase = value + tid;       // thread-owned output element
    const float4* qp = reinterpret_cast<const float4*>(q_sm[w]);

    float acc   = 0.f;
    float m_run = NEG_INF;
    float l_run = 0.f;

    for (int base = 0; base < deg; base += 32) {
        const int cnt = min(32, deg - base);

        // one coalesced eid load; lane -> its edge
        int e = (lane < cnt) ? __ldg(&g_eid[beg + base + lane]) : -1;

        // ---- score for this lane's edge (8x LDG.128, issued first) ----
        float s = NEG_INF;
        if (e >= 0) {
            const float4* kp = reinterpret_cast<const float4*>(
                key_edge + ((size_t)e * 8 + w) * 32);
            float d = 0.f;
            #pragma unroll
            for (int j = 0; j < 8; j++) {
                float4 k4 = __ldg(kp + j);
                float4 q4 = qp[j];
                d = fmaf(k4.x, q4.x, d);
                d = fmaf(k4.y, q4.y, d);
                d = fmaf(k4.z, q4.z, d);
                d = fmaf(k4.w, q4.w, d);
            }
            s = d * 0.0625f;               // 1/sqrt(256)
        }

        // ---- value prefetch: all 32 chunk edges, thread-owned element ----
        float v[32];
        #pragma unroll
        for (int i = 0; i < 32; i++) {
            int ei = __shfl_sync(0xffffffffu, e, i);
            v[i] = (ei >= 0) ? __ldg(vbase + (size_t)ei * 256) : 0.f;
        }

        // ---- warp softmax (online combine across chunks) ----
        float mloc = s;
        #pragma unroll
        for (int d2 = 16; d2 >= 1; d2 >>= 1)
            mloc = fmaxf(mloc, __shfl_xor_sync(0xffffffffu, mloc, d2));
        float m_new   = fmaxf(m_run, mloc);
        float rescale = __expf(m_run - m_new);   // 0 on first chunk
        acc   *= rescale;
        l_run *= rescale;

        float ex = (e >= 0) ? __expf(s - m_new) : 0.f;
        float lsum = ex;
        #pragma unroll
        for (int d2 = 16; d2 >= 1; d2 >>= 1)
            lsum += __shfl_xor_sync(0xffffffffu, lsum, d2);
        l_run += lsum;
        m_run = m_new;

        // ---- weighted accumulate from registers ----
        #pragma unroll
        for (int i = 0; i < 32; i++) {
            float xi = __shfl_sync(0xffffffffu, ex, i);
            acc = fmaf(xi, v[i], acc);
        }
    }

    float o = (l_run > 0.f) ? acc * (1.f / l_run) : 0.f;
    out[(size_t)n * 256 + tid] = o;
}

extern "C" void kernel_launch(void* const* d_in, const int* in_sizes, int n_in,
                              void* d_out, int out_size) {
    const float* key_edge = (const float*)d_in[0];   // [E,8,32]
    const float* q0       = (const float*)d_in[1];   // [N,64,1]
    const float* q1       = (const float*)d_in[2];   // [N,64,3]
    const float* value    = (const float*)d_in[3];   // [E,64,4]
    const int*   dst      = (const int*)d_in[4];     // [E]

    int n_edges = in_sizes[4];
    int n_nodes = in_sizes[1] / 64;
    int nb = (n_nodes + 255) / 256;

    zero_counts<<<(n_nodes + 255) / 256, 256>>>(n_nodes);
    histogram_kernel<<<(n_edges + 255) / 256, 256>>>(dst, n_edges);
    block_reduce<<<nb, 256>>>(n_nodes);
    scan_blocks<<<1, 256>>>(nb);
    scan_local<<<nb, 256>>>(n_nodes);
    scatter_edges<<<(n_edges + 255) / 256, 256>>>(dst, n_edges);
    attn_kernel<<<n_nodes, 256>>>(key_edge, q0, q1, value, (float*)d_out);
}